// round 14
// baseline (speedup 1.0000x reference)
#include <cuda_runtime.h>
#include <cuda_fp16.h>

#define NV 100000
#define NE 1000000
#define D  64

#define CAP 128              // adjacency bucket capacity per vertex
                             // (degrees ~ Poisson(20); P(deg>=128) ~ 0)

#define AS_STRIDE 80   // halves per smem row (160B, 16B-aligned, conflict-free)

__device__ __forceinline__ unsigned h2_as_uint(__half2 h) {
    return *reinterpret_cast<unsigned*>(&h);
}
__device__ __forceinline__ __half2 uint_as_h2(unsigned u) {
    return *reinterpret_cast<__half2*>(&u);
}
__device__ __forceinline__ void ldsm_x4(unsigned& r0, unsigned& r1,
                                        unsigned& r2, unsigned& r3,
                                        unsigned addr) {
    asm volatile("ldmatrix.sync.aligned.m8n8.x4.shared.b16 {%0,%1,%2,%3}, [%4];"
                 : "=r"(r0), "=r"(r1), "=r"(r2), "=r"(r3) : "r"(addr));
}
__device__ __forceinline__ void mma16816(float* d, const unsigned* a,
                                         const unsigned* b) {
    asm volatile(
        "mma.sync.aligned.m16n8k16.row.col.f32.f16.f16.f32 "
        "{%0,%1,%2,%3}, {%4,%5,%6,%7}, {%8,%9}, {%0,%1,%2,%3};"
        : "+f"(d[0]), "+f"(d[1]), "+f"(d[2]), "+f"(d[3])
        : "r"(a[0]), "r"(a[1]), "r"(a[2]), "r"(a[3]), "r"(b[0]), "r"(b[1]));
}

// Static device scratch (no allocations allowed).
// g_cur is zero-initialized at module load; the gather kernel resets it after
// consuming it, so every call (first run and every graph replay) begins with
// zeroed cursors. No separate memset kernel.
__device__ __half g_w1x_h[(size_t)NV * D];   // verts @ W1^T + b1, fp16 (12.8 MB)
__device__ int    g_cur[NV];                 // bucket cursors (= degree after fill)
__device__ int    g_adj[(size_t)NV * CAP];   // bucketed adjacency (51.2 MB)

// ---------------------------------------------------------------------------
// Tensor-core dual GEMM (fp16 HMMA, fp32 accum) + FUSED adjacency fill.
//   C[v][0:64]  -> out     (fp32, verts@W0^T + b0)
//   C[v][64:128]-> g_w1x_h (fp16, verts@W1^T + b1)
// ---------------------------------------------------------------------------
#define EDGES_PER_BLK 1280   // 782 blocks * 1280 >= NE

__global__ __launch_bounds__(256) void gemm_dual_fill_kernel(
    const float* __restrict__ verts,
    const int*   __restrict__ edges,
    const float* __restrict__ w0,
    const float* __restrict__ b0,
    const float* __restrict__ w1,
    const float* __restrict__ b1,
    float* __restrict__ out)
{
    __shared__ __half As[128 * AS_STRIDE];   // As[row][k]  20KB
    __shared__ __half Bs[128 * AS_STRIDE];   // Bs[n][k]    20KB (n<64:W0, n>=64:W1)

    const int t        = threadIdx.x;
    const int row_base = blockIdx.x * 128;

    // ---- fused adjacency fill (overflow-guarded) ---------------------------
    {
        const int e0 = blockIdx.x * EDGES_PER_BLK;
#pragma unroll
        for (int it = 0; it < EDGES_PER_BLK / 256; it++) {
            const int e = e0 + it * 256 + t;
            if (e < NE) {
                const int2 ab = __ldg(reinterpret_cast<const int2*>(edges) + e);
                const int p1 = atomicAdd(&g_cur[ab.x], 1);
                if (p1 < CAP) g_adj[(size_t)ab.x * CAP + p1] = ab.y;
                const int p2 = atomicAdd(&g_cur[ab.y], 1);
                if (p2 < CAP) g_adj[(size_t)ab.y * CAP + p2] = ab.x;
            }
        }
    }

    // ---- fill Bs: Bs[j][k] = w0[j][k]; Bs[64+j][k] = w1[j][k] (fp16) ------
    for (int i = t; i < 64 * 16; i += 256) {
        const int j  = i / 16;
        const int k4 = i % 16;
        const float4 v0 = __ldg(reinterpret_cast<const float4*>(w0) + i);
        const float4 v1 = __ldg(reinterpret_cast<const float4*>(w1) + i);
        uint2 p0, p1;
        p0.x = h2_as_uint(__floats2half2_rn(v0.x, v0.y));
        p0.y = h2_as_uint(__floats2half2_rn(v0.z, v0.w));
        p1.x = h2_as_uint(__floats2half2_rn(v1.x, v1.y));
        p1.y = h2_as_uint(__floats2half2_rn(v1.z, v1.w));
        *reinterpret_cast<uint2*>(Bs + j * AS_STRIDE + k4 * 4)        = p0;
        *reinterpret_cast<uint2*>(Bs + (64 + j) * AS_STRIDE + k4 * 4) = p1;
    }

    // ---- fill As: As[r][k] = verts[row_base+r][k] (fp16) ------------------
#pragma unroll
    for (int it = 0; it < 8; it++) {
        const int idx = it * 256 + t;
        const int r   = idx / 16;
        const int k4  = idx % 16;
        const int row = row_base + r;
        float4 v = make_float4(0.f, 0.f, 0.f, 0.f);
        if (row < NV)
            v = __ldg(reinterpret_cast<const float4*>(verts + (size_t)row * D) + k4);
        uint2 pk;
        pk.x = h2_as_uint(__floats2half2_rn(v.x, v.y));
        pk.y = h2_as_uint(__floats2half2_rn(v.z, v.w));
        *reinterpret_cast<uint2*>(As + r * AS_STRIDE + k4 * 4) = pk;
    }

    const int lane = t & 31;
    const int wid  = t >> 5;
    const int wr   = wid >> 1;
    const int wc   = wid & 1;
    const int cq   = (lane & 3) * 2;
    const int rq   = lane >> 2;

    float acc[2][8][4];
#pragma unroll
    for (int nt = 0; nt < 8; nt++) {
        const int col = wc * 64 + nt * 8 + cq;
        float be, bo;
        if (col < 64) { be = __ldg(b0 + col);      bo = __ldg(b0 + col + 1); }
        else          { be = __ldg(b1 + col - 64); bo = __ldg(b1 + col - 63); }
#pragma unroll
        for (int mt = 0; mt < 2; mt++) {
            acc[mt][nt][0] = be; acc[mt][nt][1] = bo;
            acc[mt][nt][2] = be; acc[mt][nt][3] = bo;
        }
    }
    __syncthreads();

#pragma unroll
    for (int kc = 0; kc < 4; kc++) {
        const int k = kc * 16;

        unsigned a[2][4];
#pragma unroll
        for (int mt = 0; mt < 2; mt++) {
            const __half* p = As + (wr * 32 + mt * 16 + (lane & 15)) * AS_STRIDE
                                 + k + (lane >> 4) * 8;
            ldsm_x4(a[mt][0], a[mt][1], a[mt][2], a[mt][3],
                    (unsigned)__cvta_generic_to_shared(p));
        }

        unsigned b[8][2];
#pragma unroll
        for (int ntp = 0; ntp < 4; ntp++) {
            const int n0     = wc * 64 + ntp * 16;
            const int group  = lane >> 3;
            const int within = lane & 7;
            const __half* p = Bs + (n0 + within + (group >> 1) * 8) * AS_STRIDE
                                 + k + (group & 1) * 8;
            unsigned r0, r1, r2, r3;
            ldsm_x4(r0, r1, r2, r3, (unsigned)__cvta_generic_to_shared(p));
            b[2 * ntp][0]     = r0;  b[2 * ntp][1]     = r1;
            b[2 * ntp + 1][0] = r2;  b[2 * ntp + 1][1] = r3;
        }

#pragma unroll
        for (int mt = 0; mt < 2; mt++)
#pragma unroll
            for (int nt = 0; nt < 8; nt++)
                mma16816(acc[mt][nt], a[mt], b[nt]);
    }

    // ---- epilogue: fragment-direct stores ---------------------------------
#pragma unroll
    for (int mt = 0; mt < 2; mt++) {
        const int rbase = wr * 32 + mt * 16;
#pragma unroll
        for (int h = 0; h < 2; h++) {
            const int r = row_base + rbase + rq + h * 8;
            if (r >= NV) continue;
#pragma unroll
            for (int nt = 0; nt < 8; nt++) {
                const int col = wc * 64 + nt * 8 + cq;
                const float e = acc[mt][nt][h * 2 + 0];
                const float o = acc[mt][nt][h * 2 + 1];
                if (col < 64) {
                    *reinterpret_cast<float2*>(out + (size_t)r * D + col) =
                        make_float2(e, o);
                } else {
                    *reinterpret_cast<__half2*>(g_w1x_h + (size_t)r * D + col - 64) =
                        __floats2half2_rn(e, o);
                }
            }
        }
    }
}

// ---------------------------------------------------------------------------
// Bucket gather (fp16 rows, fp32 accumulate): out[v] += sum_{u} w1x[u]
// 8 threads per vertex, each owns a 16B chunk (8 halves) of the 128B row.
// Scalar adjacency loads (keeps MLP), unroll-8 batches.
// After reading deg (one warp-wide LDG), lane j==0 resets the cursor so the
// next kernel_launch call starts from zeroed g_cur — replaces the memset
// kernel. All 8 lanes read deg in the same instruction before the store.
// ---------------------------------------------------------------------------
__global__ __launch_bounds__(256) void gather_kernel(float* __restrict__ out)
{
    const int t = threadIdx.x;
    const int v = blockIdx.x * 32 + (t >> 3);
    const int j = t & 7;                    // 16B chunk index
    if (v >= NV) return;

    int deg = g_cur[v];
    if (deg > CAP) deg = CAP;
    if (j == 0) g_cur[v] = 0;               // re-arm for the next call

    const int* adj = g_adj + (size_t)v * CAP;

    float a0 = 0.f, a1 = 0.f, a2 = 0.f, a3 = 0.f;
    float a4 = 0.f, a5 = 0.f, a6 = 0.f, a7 = 0.f;

#define ACC_ROW(u)                                                              \
    {                                                                           \
        const uint4 pk = __ldg(reinterpret_cast<const uint4*>(                  \
                                   g_w1x_h + (size_t)(u) * D) + j);             \
        const float2 f0 = __half22float2(uint_as_h2(pk.x));                     \
        const float2 f1 = __half22float2(uint_as_h2(pk.y));                     \
        const float2 f2 = __half22float2(uint_as_h2(pk.z));                     \
        const float2 f3 = __half22float2(uint_as_h2(pk.w));                     \
        a0 += f0.x; a1 += f0.y; a2 += f1.x; a3 += f1.y;                         \
        a4 += f2.x; a5 += f2.y; a6 += f3.x; a7 += f3.y;                         \
    }

    int p = 0;
    for (; p + 8 <= deg; p += 8) {
        const int u0 = __ldg(adj + p + 0);
        const int u1 = __ldg(adj + p + 1);
        const int u2 = __ldg(adj + p + 2);
        const int u3 = __ldg(adj + p + 3);
        const int u4 = __ldg(adj + p + 4);
        const int u5 = __ldg(adj + p + 5);
        const int u6 = __ldg(adj + p + 6);
        const int u7 = __ldg(adj + p + 7);
        ACC_ROW(u0); ACC_ROW(u1); ACC_ROW(u2); ACC_ROW(u3);
        ACC_ROW(u4); ACC_ROW(u5); ACC_ROW(u6); ACC_ROW(u7);
    }
    if (p + 4 <= deg) {
        const int u0 = __ldg(adj + p + 0);
        const int u1 = __ldg(adj + p + 1);
        const int u2 = __ldg(adj + p + 2);
        const int u3 = __ldg(adj + p + 3);
        ACC_ROW(u0); ACC_ROW(u1); ACC_ROW(u2); ACC_ROW(u3);
        p += 4;
    }
    for (; p < deg; p++) {
        const int u = __ldg(adj + p);
        ACC_ROW(u);
    }
#undef ACC_ROW

    float4* o = reinterpret_cast<float4*>(out + (size_t)v * D + j * 8);
    float4 c0 = o[0], c1 = o[1];
    c0.x += a0; c0.y += a1; c0.z += a2; c0.w += a3;
    c1.x += a4; c1.y += a5; c1.z += a6; c1.w += a7;
    o[0] = c0;
    o[1] = c1;
}

// ---------------------------------------------------------------------------
// Launch: 2 kernels. gemm(+fill) -> gather(+cursor re-arm).
// ---------------------------------------------------------------------------
extern "C" void kernel_launch(void* const* d_in, const int* in_sizes, int n_in,
                              void* d_out, int out_size)
{
    const float* verts = (const float*)d_in[0];
    const int*   edges = (const int*)d_in[1];
    const float* w0w   = (const float*)d_in[2];
    const float* w0b   = (const float*)d_in[3];
    const float* w1w   = (const float*)d_in[4];
    const float* w1b   = (const float*)d_in[5];
    float*       out   = (float*)d_out;

    gemm_dual_fill_kernel<<<(NV + 127) / 128, 256>>>(verts, edges, w0w, w0b, w1w, w1b, out);
    gather_kernel<<<(NV + 31) / 32, 256>>>(out);
}

// round 15
// speedup vs baseline: 1.0878x; 1.0878x over previous
#include <cuda_runtime.h>
#include <cuda_fp16.h>

#define NV 100000
#define NE 1000000
#define D  64

#define CAP 128              // adjacency bucket capacity per vertex
                             // (degrees ~ Poisson(20); P(deg>=128) ~ 0)

#define AS_STRIDE 80   // halves per smem row (160B, 16B-aligned, conflict-free)

__device__ __forceinline__ unsigned h2_as_uint(__half2 h) {
    return *reinterpret_cast<unsigned*>(&h);
}
__device__ __forceinline__ __half2 uint_as_h2(unsigned u) {
    return *reinterpret_cast<__half2*>(&u);
}
__device__ __forceinline__ void ldsm_x4(unsigned& r0, unsigned& r1,
                                        unsigned& r2, unsigned& r3,
                                        unsigned addr) {
    asm volatile("ldmatrix.sync.aligned.m8n8.x4.shared.b16 {%0,%1,%2,%3}, [%4];"
                 : "=r"(r0), "=r"(r1), "=r"(r2), "=r"(r3) : "r"(addr));
}
__device__ __forceinline__ void mma16816(float* d, const unsigned* a,
                                         const unsigned* b) {
    asm volatile(
        "mma.sync.aligned.m16n8k16.row.col.f32.f16.f16.f32 "
        "{%0,%1,%2,%3}, {%4,%5,%6,%7}, {%8,%9}, {%0,%1,%2,%3};"
        : "+f"(d[0]), "+f"(d[1]), "+f"(d[2]), "+f"(d[3])
        : "r"(a[0]), "r"(a[1]), "r"(a[2]), "r"(a[3]), "r"(b[0]), "r"(b[1]));
}

// Static device scratch (no allocations allowed)
__device__ __half g_w1x_h[(size_t)NV * D];   // verts @ W1^T + b1, fp16 (12.8 MB)
__device__ int    g_cur[NV];                 // bucket cursors (= degree after fill)
__device__ int    g_adj[(size_t)NV * CAP];   // bucketed adjacency (51.2 MB)

// ---------------------------------------------------------------------------
// Tensor-core dual GEMM (fp16 HMMA, fp32 accum) + FUSED adjacency fill.
//   C[v][0:64]  -> out     (fp32, verts@W0^T + b0)
//   C[v][64:128]-> g_w1x_h (fp16, verts@W1^T + b1)
// ---------------------------------------------------------------------------
#define EDGES_PER_BLK 1280   // 782 blocks * 1280 >= NE

__global__ __launch_bounds__(256) void gemm_dual_fill_kernel(
    const float* __restrict__ verts,
    const int*   __restrict__ edges,
    const float* __restrict__ w0,
    const float* __restrict__ b0,
    const float* __restrict__ w1,
    const float* __restrict__ b1,
    float* __restrict__ out)
{
    __shared__ __half As[128 * AS_STRIDE];   // As[row][k]  20KB
    __shared__ __half Bs[128 * AS_STRIDE];   // Bs[n][k]    20KB (n<64:W0, n>=64:W1)

    const int t        = threadIdx.x;
    const int row_base = blockIdx.x * 128;

    // ---- fused adjacency fill ---------------------------------------------
    {
        const int e0 = blockIdx.x * EDGES_PER_BLK;
#pragma unroll
        for (int it = 0; it < EDGES_PER_BLK / 256; it++) {
            const int e = e0 + it * 256 + t;
            if (e < NE) {
                const int2 ab = __ldg(reinterpret_cast<const int2*>(edges) + e);
                const int p1 = atomicAdd(&g_cur[ab.x], 1);
                g_adj[(size_t)ab.x * CAP + p1] = ab.y;
                const int p2 = atomicAdd(&g_cur[ab.y], 1);
                g_adj[(size_t)ab.y * CAP + p2] = ab.x;
            }
        }
    }

    // ---- fill Bs: Bs[j][k] = w0[j][k]; Bs[64+j][k] = w1[j][k] (fp16) ------
    for (int i = t; i < 64 * 16; i += 256) {
        const int j  = i / 16;
        const int k4 = i % 16;
        const float4 v0 = __ldg(reinterpret_cast<const float4*>(w0) + i);
        const float4 v1 = __ldg(reinterpret_cast<const float4*>(w1) + i);
        uint2 p0, p1;
        p0.x = h2_as_uint(__floats2half2_rn(v0.x, v0.y));
        p0.y = h2_as_uint(__floats2half2_rn(v0.z, v0.w));
        p1.x = h2_as_uint(__floats2half2_rn(v1.x, v1.y));
        p1.y = h2_as_uint(__floats2half2_rn(v1.z, v1.w));
        *reinterpret_cast<uint2*>(Bs + j * AS_STRIDE + k4 * 4)        = p0;
        *reinterpret_cast<uint2*>(Bs + (64 + j) * AS_STRIDE + k4 * 4) = p1;
    }

    // ---- fill As: As[r][k] = verts[row_base+r][k] (fp16) ------------------
#pragma unroll
    for (int it = 0; it < 8; it++) {
        const int idx = it * 256 + t;
        const int r   = idx / 16;
        const int k4  = idx % 16;
        const int row = row_base + r;
        float4 v = make_float4(0.f, 0.f, 0.f, 0.f);
        if (row < NV)
            v = __ldg(reinterpret_cast<const float4*>(verts + (size_t)row * D) + k4);
        uint2 pk;
        pk.x = h2_as_uint(__floats2half2_rn(v.x, v.y));
        pk.y = h2_as_uint(__floats2half2_rn(v.z, v.w));
        *reinterpret_cast<uint2*>(As + r * AS_STRIDE + k4 * 4) = pk;
    }

    const int lane = t & 31;
    const int wid  = t >> 5;
    const int wr   = wid >> 1;
    const int wc   = wid & 1;
    const int cq   = (lane & 3) * 2;
    const int rq   = lane >> 2;

    float acc[2][8][4];
#pragma unroll
    for (int nt = 0; nt < 8; nt++) {
        const int col = wc * 64 + nt * 8 + cq;
        float be, bo;
        if (col < 64) { be = __ldg(b0 + col);      bo = __ldg(b0 + col + 1); }
        else          { be = __ldg(b1 + col - 64); bo = __ldg(b1 + col - 63); }
#pragma unroll
        for (int mt = 0; mt < 2; mt++) {
            acc[mt][nt][0] = be; acc[mt][nt][1] = bo;
            acc[mt][nt][2] = be; acc[mt][nt][3] = bo;
        }
    }
    __syncthreads();

#pragma unroll
    for (int kc = 0; kc < 4; kc++) {
        const int k = kc * 16;

        unsigned a[2][4];
#pragma unroll
        for (int mt = 0; mt < 2; mt++) {
            const __half* p = As + (wr * 32 + mt * 16 + (lane & 15)) * AS_STRIDE
                                 + k + (lane >> 4) * 8;
            ldsm_x4(a[mt][0], a[mt][1], a[mt][2], a[mt][3],
                    (unsigned)__cvta_generic_to_shared(p));
        }

        unsigned b[8][2];
#pragma unroll
        for (int ntp = 0; ntp < 4; ntp++) {
            const int n0     = wc * 64 + ntp * 16;
            const int group  = lane >> 3;
            const int within = lane & 7;
            const __half* p = Bs + (n0 + within + (group >> 1) * 8) * AS_STRIDE
                                 + k + (group & 1) * 8;
            unsigned r0, r1, r2, r3;
            ldsm_x4(r0, r1, r2, r3, (unsigned)__cvta_generic_to_shared(p));
            b[2 * ntp][0]     = r0;  b[2 * ntp][1]     = r1;
            b[2 * ntp + 1][0] = r2;  b[2 * ntp + 1][1] = r3;
        }

#pragma unroll
        for (int mt = 0; mt < 2; mt++)
#pragma unroll
            for (int nt = 0; nt < 8; nt++)
                mma16816(acc[mt][nt], a[mt], b[nt]);
    }

    // ---- epilogue: fragment-direct stores ---------------------------------
#pragma unroll
    for (int mt = 0; mt < 2; mt++) {
        const int rbase = wr * 32 + mt * 16;
#pragma unroll
        for (int h = 0; h < 2; h++) {
            const int r = row_base + rbase + rq + h * 8;
            if (r >= NV) continue;
#pragma unroll
            for (int nt = 0; nt < 8; nt++) {
                const int col = wc * 64 + nt * 8 + cq;
                const float e = acc[mt][nt][h * 2 + 0];
                const float o = acc[mt][nt][h * 2 + 1];
                if (col < 64) {
                    *reinterpret_cast<float2*>(out + (size_t)r * D + col) =
                        make_float2(e, o);
                } else {
                    *reinterpret_cast<__half2*>(g_w1x_h + (size_t)r * D + col - 64) =
                        __floats2half2_rn(e, o);
                }
            }
        }
    }
}

// ---------------------------------------------------------------------------
// Bucket gather (fp16 rows, fp32 accumulate): out[v] += sum_{u} w1x[u]
// 8 threads per vertex, each owns a 16B chunk (8 halves) of the 128B row.
// Scalar adjacency loads, unroll-4 (the measured-best R9 configuration).
// ---------------------------------------------------------------------------
__global__ __launch_bounds__(256) void gather_kernel(float* __restrict__ out)
{
    const int t = threadIdx.x;
    const int v = blockIdx.x * 32 + (t >> 3);
    const int j = t & 7;                    // 16B chunk index
    if (v >= NV) return;

    const int deg = g_cur[v];
    const int* adj = g_adj + (size_t)v * CAP;

    float a0 = 0.f, a1 = 0.f, a2 = 0.f, a3 = 0.f;
    float a4 = 0.f, a5 = 0.f, a6 = 0.f, a7 = 0.f;

#define ACC_ROW(u)                                                              \
    {                                                                           \
        const uint4 pk = __ldg(reinterpret_cast<const uint4*>(                  \
                                   g_w1x_h + (size_t)(u) * D) + j);             \
        const float2 f0 = __half22float2(uint_as_h2(pk.x));                     \
        const float2 f1 = __half22float2(uint_as_h2(pk.y));                     \
        const float2 f2 = __half22float2(uint_as_h2(pk.z));                     \
        const float2 f3 = __half22float2(uint_as_h2(pk.w));                     \
        a0 += f0.x; a1 += f0.y; a2 += f1.x; a3 += f1.y;                         \
        a4 += f2.x; a5 += f2.y; a6 += f3.x; a7 += f3.y;                         \
    }

    int p = 0;
    for (; p + 4 <= deg; p += 4) {
        const int u0 = __ldg(adj + p + 0);
        const int u1 = __ldg(adj + p + 1);
        const int u2 = __ldg(adj + p + 2);
        const int u3 = __ldg(adj + p + 3);
        ACC_ROW(u0); ACC_ROW(u1); ACC_ROW(u2); ACC_ROW(u3);
    }
    for (; p < deg; p++) {
        const int u = __ldg(adj + p);
        ACC_ROW(u);
    }
#undef ACC_ROW

    float4* o = reinterpret_cast<float4*>(out + (size_t)v * D + j * 8);
    float4 c0 = o[0], c1 = o[1];
    c0.x += a0; c0.y += a1; c0.z += a2; c0.w += a3;
    c1.x += a4; c1.y += a5; c1.z += a6; c1.w += a7;
    o[0] = c0;
    o[1] = c1;
}

// ---------------------------------------------------------------------------
// Launch: memset node (cursor zeroing) -> gemm(+fill) -> gather.
// cudaMemsetAsync is graph-capturable (memset node) and not an allocation.
// ---------------------------------------------------------------------------
extern "C" void kernel_launch(void* const* d_in, const int* in_sizes, int n_in,
                              void* d_out, int out_size)
{
    const float* verts = (const float*)d_in[0];
    const int*   edges = (const int*)d_in[1];
    const float* w0w   = (const float*)d_in[2];
    const float* w0b   = (const float*)d_in[3];
    const float* w1w   = (const float*)d_in[4];
    const float* w1b   = (const float*)d_in[5];
    float*       out   = (float*)d_out;

    static void* cur_ptr = nullptr;
    if (cur_ptr == nullptr)
        cudaGetSymbolAddress(&cur_ptr, g_cur);

    cudaMemsetAsync(cur_ptr, 0, NV * sizeof(int));
    gemm_dual_fill_kernel<<<(NV + 127) / 128, 256>>>(verts, edges, w0w, w0b, w1w, w1b, out);
    gather_kernel<<<(NV + 31) / 32, 256>>>(out);
}

// round 16
// speedup vs baseline: 1.1083x; 1.0188x over previous
#include <cuda_runtime.h>
#include <cuda_fp16.h>

#define NV 100000
#define NE 1000000
#define D  64

#define CAP 128              // adjacency bucket capacity per vertex
                             // (degrees ~ Poisson(20); P(deg>=128) ~ 0)

#define AS_STRIDE 80   // halves per smem row (160B, 16B-aligned, conflict-free)

__device__ __forceinline__ unsigned h2_as_uint(__half2 h) {
    return *reinterpret_cast<unsigned*>(&h);
}
__device__ __forceinline__ __half2 uint_as_h2(unsigned u) {
    return *reinterpret_cast<__half2*>(&u);
}
__device__ __forceinline__ void ldsm_x4(unsigned& r0, unsigned& r1,
                                        unsigned& r2, unsigned& r3,
                                        unsigned addr) {
    asm volatile("ldmatrix.sync.aligned.m8n8.x4.shared.b16 {%0,%1,%2,%3}, [%4];"
                 : "=r"(r0), "=r"(r1), "=r"(r2), "=r"(r3) : "r"(addr));
}
__device__ __forceinline__ void mma16816(float* d, const unsigned* a,
                                         const unsigned* b) {
    asm volatile(
        "mma.sync.aligned.m16n8k16.row.col.f32.f16.f16.f32 "
        "{%0,%1,%2,%3}, {%4,%5,%6,%7}, {%8,%9}, {%0,%1,%2,%3};"
        : "+f"(d[0]), "+f"(d[1]), "+f"(d[2]), "+f"(d[3])
        : "r"(a[0]), "r"(a[1]), "r"(a[2]), "r"(a[3]), "r"(b[0]), "r"(b[1]));
}

// Static device scratch (no allocations allowed)
__device__ __half g_w1x_h[(size_t)NV * D];   // verts @ W1^T + b1, fp16 (12.8 MB)
__device__ int    g_cur[NV];                 // bucket cursors (= degree after fill)
__device__ int    g_adj[(size_t)NV * CAP];   // bucketed adjacency (51.2 MB)

// ---------------------------------------------------------------------------
// Tensor-core dual GEMM (fp16 HMMA, fp32 accum) + FUSED adjacency fill.
//   C[v][0:64]  -> out     (fp32, verts@W0^T + b0)
//   C[v][64:128]-> g_w1x_h (fp16, verts@W1^T + b1)
// ---------------------------------------------------------------------------
#define EDGES_PER_BLK 1280   // 782 blocks * 1280 >= NE

__global__ __launch_bounds__(256) void gemm_dual_fill_kernel(
    const float* __restrict__ verts,
    const int*   __restrict__ edges,
    const float* __restrict__ w0,
    const float* __restrict__ b0,
    const float* __restrict__ w1,
    const float* __restrict__ b1,
    float* __restrict__ out)
{
    __shared__ __half As[128 * AS_STRIDE];   // As[row][k]  20KB
    __shared__ __half Bs[128 * AS_STRIDE];   // Bs[n][k]    20KB (n<64:W0, n>=64:W1)

    const int t        = threadIdx.x;
    const int row_base = blockIdx.x * 128;

    // ---- fused adjacency fill ---------------------------------------------
    {
        const int e0 = blockIdx.x * EDGES_PER_BLK;
#pragma unroll
        for (int it = 0; it < EDGES_PER_BLK / 256; it++) {
            const int e = e0 + it * 256 + t;
            if (e < NE) {
                const int2 ab = __ldg(reinterpret_cast<const int2*>(edges) + e);
                const int p1 = atomicAdd(&g_cur[ab.x], 1);
                g_adj[(size_t)ab.x * CAP + p1] = ab.y;
                const int p2 = atomicAdd(&g_cur[ab.y], 1);
                g_adj[(size_t)ab.y * CAP + p2] = ab.x;
            }
        }
    }

    // ---- fill Bs: Bs[j][k] = w0[j][k]; Bs[64+j][k] = w1[j][k] (fp16) ------
    for (int i = t; i < 64 * 16; i += 256) {
        const int j  = i / 16;
        const int k4 = i % 16;
        const float4 v0 = __ldg(reinterpret_cast<const float4*>(w0) + i);
        const float4 v1 = __ldg(reinterpret_cast<const float4*>(w1) + i);
        uint2 p0, p1;
        p0.x = h2_as_uint(__floats2half2_rn(v0.x, v0.y));
        p0.y = h2_as_uint(__floats2half2_rn(v0.z, v0.w));
        p1.x = h2_as_uint(__floats2half2_rn(v1.x, v1.y));
        p1.y = h2_as_uint(__floats2half2_rn(v1.z, v1.w));
        *reinterpret_cast<uint2*>(Bs + j * AS_STRIDE + k4 * 4)        = p0;
        *reinterpret_cast<uint2*>(Bs + (64 + j) * AS_STRIDE + k4 * 4) = p1;
    }

    // ---- fill As: As[r][k] = verts[row_base+r][k] (fp16) ------------------
#pragma unroll
    for (int it = 0; it < 8; it++) {
        const int idx = it * 256 + t;
        const int r   = idx / 16;
        const int k4  = idx % 16;
        const int row = row_base + r;
        float4 v = make_float4(0.f, 0.f, 0.f, 0.f);
        if (row < NV)
            v = __ldg(reinterpret_cast<const float4*>(verts + (size_t)row * D) + k4);
        uint2 pk;
        pk.x = h2_as_uint(__floats2half2_rn(v.x, v.y));
        pk.y = h2_as_uint(__floats2half2_rn(v.z, v.w));
        *reinterpret_cast<uint2*>(As + r * AS_STRIDE + k4 * 4) = pk;
    }

    const int lane = t & 31;
    const int wid  = t >> 5;
    const int wr   = wid >> 1;
    const int wc   = wid & 1;
    const int cq   = (lane & 3) * 2;
    const int rq   = lane >> 2;

    float acc[2][8][4];
#pragma unroll
    for (int nt = 0; nt < 8; nt++) {
        const int col = wc * 64 + nt * 8 + cq;
        float be, bo;
        if (col < 64) { be = __ldg(b0 + col);      bo = __ldg(b0 + col + 1); }
        else          { be = __ldg(b1 + col - 64); bo = __ldg(b1 + col - 63); }
#pragma unroll
        for (int mt = 0; mt < 2; mt++) {
            acc[mt][nt][0] = be; acc[mt][nt][1] = bo;
            acc[mt][nt][2] = be; acc[mt][nt][3] = bo;
        }
    }
    __syncthreads();

#pragma unroll
    for (int kc = 0; kc < 4; kc++) {
        const int k = kc * 16;

        unsigned a[2][4];
#pragma unroll
        for (int mt = 0; mt < 2; mt++) {
            const __half* p = As + (wr * 32 + mt * 16 + (lane & 15)) * AS_STRIDE
                                 + k + (lane >> 4) * 8;
            ldsm_x4(a[mt][0], a[mt][1], a[mt][2], a[mt][3],
                    (unsigned)__cvta_generic_to_shared(p));
        }

        unsigned b[8][2];
#pragma unroll
        for (int ntp = 0; ntp < 4; ntp++) {
            const int n0     = wc * 64 + ntp * 16;
            const int group  = lane >> 3;
            const int within = lane & 7;
            const __half* p = Bs + (n0 + within + (group >> 1) * 8) * AS_STRIDE
                                 + k + (group & 1) * 8;
            unsigned r0, r1, r2, r3;
            ldsm_x4(r0, r1, r2, r3, (unsigned)__cvta_generic_to_shared(p));
            b[2 * ntp][0]     = r0;  b[2 * ntp][1]     = r1;
            b[2 * ntp + 1][0] = r2;  b[2 * ntp + 1][1] = r3;
        }

#pragma unroll
        for (int mt = 0; mt < 2; mt++)
#pragma unroll
            for (int nt = 0; nt < 8; nt++)
                mma16816(acc[mt][nt], a[mt], b[nt]);
    }

    // ---- epilogue: fragment-direct stores ---------------------------------
#pragma unroll
    for (int mt = 0; mt < 2; mt++) {
        const int rbase = wr * 32 + mt * 16;
#pragma unroll
        for (int h = 0; h < 2; h++) {
            const int r = row_base + rbase + rq + h * 8;
            if (r >= NV) continue;
#pragma unroll
            for (int nt = 0; nt < 8; nt++) {
                const int col = wc * 64 + nt * 8 + cq;
                const float e = acc[mt][nt][h * 2 + 0];
                const float o = acc[mt][nt][h * 2 + 1];
                if (col < 64) {
                    *reinterpret_cast<float2*>(out + (size_t)r * D + col) =
                        make_float2(e, o);
                } else {
                    *reinterpret_cast<__half2*>(g_w1x_h + (size_t)r * D + col - 64) =
                        __floats2half2_rn(e, o);
                }
            }
        }
    }
}

// ---------------------------------------------------------------------------
// Bucket gather (fp16 rows, fp32 accumulate): out[v] += sum_{u} w1x[u]
// 16 threads per vertex, each owns an 8B chunk (4 halves) of the 128B row.
// Same serial-chain structure as the proven 8-thread version, but 2x the
// warps (50K) for latency hiding, and ~28 regs -> full occupancy.
// ---------------------------------------------------------------------------
__global__ __launch_bounds__(256) void gather_kernel(float* __restrict__ out)
{
    const int t = threadIdx.x;
    const int v = blockIdx.x * 16 + (t >> 4);
    const int j = t & 15;                   // 8B chunk index
    if (v >= NV) return;

    const int deg = g_cur[v];
    const int* adj = g_adj + (size_t)v * CAP;

    float a0 = 0.f, a1 = 0.f, a2 = 0.f, a3 = 0.f;

#define ACC_ROW(u)                                                              \
    {                                                                           \
        const uint2 pk = __ldg(reinterpret_cast<const uint2*>(                  \
                                   g_w1x_h + (size_t)(u) * D) + j);             \
        const float2 f0 = __half22float2(uint_as_h2(pk.x));                     \
        const float2 f1 = __half22float2(uint_as_h2(pk.y));                     \
        a0 += f0.x; a1 += f0.y; a2 += f1.x; a3 += f1.y;                         \
    }

    int p = 0;
    for (; p + 4 <= deg; p += 4) {
        const int u0 = __ldg(adj + p + 0);
        const int u1 = __ldg(adj + p + 1);
        const int u2 = __ldg(adj + p + 2);
        const int u3 = __ldg(adj + p + 3);
        ACC_ROW(u0); ACC_ROW(u1); ACC_ROW(u2); ACC_ROW(u3);
    }
    for (; p < deg; p++) {
        const int u = __ldg(adj + p);
        ACC_ROW(u);
    }
#undef ACC_ROW

    float4* o = reinterpret_cast<float4*>(out + (size_t)v * D + j * 4);
    float4 c = *o;
    c.x += a0; c.y += a1; c.z += a2; c.w += a3;
    *o = c;
}

// ---------------------------------------------------------------------------
// Launch: memset node (cursor zeroing) -> gemm(+fill) -> gather.
// cudaMemsetAsync is graph-capturable (memset node) and not an allocation.
// ---------------------------------------------------------------------------
extern "C" void kernel_launch(void* const* d_in, const int* in_sizes, int n_in,
                              void* d_out, int out_size)
{
    const float* verts = (const float*)d_in[0];
    const int*   edges = (const int*)d_in[1];
    const float* w0w   = (const float*)d_in[2];
    const float* w0b   = (const float*)d_in[3];
    const float* w1w   = (const float*)d_in[4];
    const float* w1b   = (const float*)d_in[5];
    float*       out   = (float*)d_out;

    static void* cur_ptr = nullptr;
    if (cur_ptr == nullptr)
        cudaGetSymbolAddress(&cur_ptr, g_cur);

    cudaMemsetAsync(cur_ptr, 0, NV * sizeof(int));
    gemm_dual_fill_kernel<<<(NV + 127) / 128, 256>>>(verts, edges, w0w, w0b, w1w, w1b, out);
    gather_kernel<<<(NV + 15) / 16, 256>>>(out);
}